// round 16
// baseline (speedup 1.0000x reference)
#include <cuda_runtime.h>
#include <cuda_bf16.h>
#include <cstdint>

#define NMAX   100000
#define EMAX   500000
#define DIM    128
#define NHEAD  4
#define HD     32
#define NBLK   391          // ceil(NMAX/256)

// ---------------- scratch ----------------
__device__ float g_h32[NMAX * HD];
__device__ float g_eas[NMAX * NHEAD];
__device__ float g_ead[NMAX * NHEAD];
__device__ float g_sums[NHEAD];
__device__ int   g_is64;
__device__ int   g_cnt[NMAX];
__device__ int   g_intra[NMAX];
__device__ int   g_bsum[512];
__device__ int   g_boff[512];
__device__ int2  g_sd[EMAX];
__device__ int   g_rk[EMAX];
__device__ int   g_esrc[EMAX];
// W fragments, per-lane mma layout: [split][ks][nt][lane][reg] u32 (64KB)
__device__ __align__(16) uint32_t g_Bfrag[2 * 8 * 16 * 32 * 2];

// ---------------- K0: prep (s1: Bfrag build + counters + sniff) ----------------
__global__ void prep_kernel(const float* __restrict__ Wlin,
                            const unsigned int* __restrict__ ei_raw) {
    int tid = blockIdx.x * blockDim.x + threadIdx.x;
    int total = gridDim.x * blockDim.x;
    for (int i = tid; i < NMAX; i += total) g_cnt[i] = 0;
    for (int i = tid; i < 16384; i += total) {
        int reg   = i & 1;
        int lane  = (i >> 1) & 31;
        int nt    = (i >> 6) & 15;
        int ks    = (i >> 10) & 7;
        int split = i >> 13;
        int n  = nt * 8 + (lane >> 2);
        int k0 = ks * 16 + (lane & 3) * 2 + reg * 8;
        float w0 = Wlin[n * DIM + k0];
        float w1 = Wlin[n * DIM + k0 + 1];
        unsigned short b0, b1;
        if (split == 0) {
            __nv_bfloat16 h0 = __float2bfloat16_rn(w0);
            __nv_bfloat16 h1 = __float2bfloat16_rn(w1);
            b0 = *(unsigned short*)&h0; b1 = *(unsigned short*)&h1;
        } else {
            __nv_bfloat16 h0 = __float2bfloat16_rn(w0);
            __nv_bfloat16 h1 = __float2bfloat16_rn(w1);
            __nv_bfloat16 l0 = __float2bfloat16_rn(w0 - __bfloat162float(h0));
            __nv_bfloat16 l1 = __float2bfloat16_rn(w1 - __bfloat162float(h1));
            b0 = *(unsigned short*)&l0; b1 = *(unsigned short*)&l1;
        }
        g_Bfrag[i] = (uint32_t)b0 | ((uint32_t)b1 << 16);
    }
    if (blockIdx.x == 0) {
        if (threadIdx.x < NHEAD) g_sums[threadIdx.x] = 0.0f;
        if (threadIdx.x == 0) {
            int all0 = 1;
            for (int i = 0; i < 64; i++)
                if (ei_raw[2 * i + 1] != 0u) { all0 = 0; break; }
            g_is64 = all0;
        }
    }
}

// ---------------- K1: persistent mma.sync bf16 3-product GEMM, 512 threads ----------------
// smem: Bfrag [0,64K) staged ONCE per CTA; Xhi [64K,96K); Xlo [96K,128K)
// epilogue ht f32[128][132] reuses [64K, 64K+67584)
#define BF_OFF  0
#define XHI_OFF 65536
#define XLO_OFF 98304
#define HT_STRIDE 132
#define GS_TOTAL (65536 + 128 * HT_STRIDE * 4)
#define PERSIST_TC 148
#define TCTHREADS 512

__device__ __forceinline__ uint32_t smem_u32(const void* p) {
    uint32_t a;
    asm("{ .reg .u64 t; cvta.to.shared.u64 t, %1; cvt.u32.u64 %0, t; }" : "=r"(a) : "l"(p));
    return a;
}

// 16B-granule XOR swizzle in a 128x128-bf16 tile (row stride 256B)
__device__ __forceinline__ uint32_t xoff(int row, int ch) {
    return (uint32_t)(row * 256 + ((ch ^ (row & 7)) << 4));
}

__device__ __forceinline__ void split8(const float4& a, const float4& b,
                                       uint4& hi, uint4& lo) {
    float v[8] = {a.x, a.y, a.z, a.w, b.x, b.y, b.z, b.w};
    unsigned short h[8], l[8];
    #pragma unroll
    for (int i = 0; i < 8; i++) {
        __nv_bfloat16 bh = __float2bfloat16_rn(v[i]);
        float r = v[i] - __bfloat162float(bh);
        __nv_bfloat16 bl = __float2bfloat16_rn(r);
        h[i] = *(unsigned short*)&bh;
        l[i] = *(unsigned short*)&bl;
    }
    hi = make_uint4((uint32_t)h[0] | ((uint32_t)h[1] << 16),
                    (uint32_t)h[2] | ((uint32_t)h[3] << 16),
                    (uint32_t)h[4] | ((uint32_t)h[5] << 16),
                    (uint32_t)h[6] | ((uint32_t)h[7] << 16));
    lo = make_uint4((uint32_t)l[0] | ((uint32_t)l[1] << 16),
                    (uint32_t)l[2] | ((uint32_t)l[3] << 16),
                    (uint32_t)l[4] | ((uint32_t)l[5] << 16),
                    (uint32_t)l[6] | ((uint32_t)l[7] << 16));
}

#define LDMATRIX4(f, addr) \
    asm volatile("ldmatrix.sync.aligned.m8n8.x4.shared.b16 {%0,%1,%2,%3}, [%4];" \
        : "=r"((f)[0]), "=r"((f)[1]), "=r"((f)[2]), "=r"((f)[3]) : "r"(addr))

#define MMA_BF16(d, a, b) \
    asm volatile("mma.sync.aligned.m16n8k16.row.col.f32.bf16.bf16.f32 " \
        "{%0,%1,%2,%3}, {%4,%5,%6,%7}, {%8,%9}, {%0,%1,%2,%3};" \
        : "+f"((d)[0]), "+f"((d)[1]), "+f"((d)[2]), "+f"((d)[3]) \
        : "r"((a)[0]), "r"((a)[1]), "r"((a)[2]), "r"((a)[3]), \
          "r"((b)[0]), "r"((b)[1]))

__global__ __launch_bounds__(TCTHREADS)
void gemm_kernel(const float* __restrict__ X,
                 const float* __restrict__ blin,
                 const float* __restrict__ Watt,
                 float* __restrict__ out, int N, int NT) {
    extern __shared__ char smem[];
    float* ht = (float*)(smem + XHI_OFF);
    __shared__ float sWa[NHEAD * 2 * DIM];
    __shared__ float sb[DIM];
    uint32_t sbase = smem_u32(smem);
    int tid = threadIdx.x;
    int wid = tid >> 5, lane = tid & 31;
    int wm = wid >> 2, wn = wid & 3;      // 16 warps: warp tile m32 x n32

    for (int i = tid; i < NHEAD * 2 * DIM; i += TCTHREADS) sWa[i] = Watt[i];
    if (tid < DIM) sb[tid] = blin[tid];

    // stage W fragments ONCE per persistent CTA (64KB)
    {
        const uint4* src = (const uint4*)g_Bfrag;
        uint4* dst = (uint4*)(smem + BF_OFF);
        for (int i = tid; i < 4096; i += TCTHREADS) dst[i] = src[i];
    }

    for (int tile = blockIdx.x; tile < NT; tile += gridDim.x) {
        int row0 = tile * 128;

        __syncthreads();   // previous tile's ht reads done

        // load + split X tile into Xhi/Xlo swizzled smem
        for (int i = tid; i < 2048; i += TCTHREADS) {
            int row = i >> 4, ch = i & 15;
            float4 x0 = make_float4(0.f, 0.f, 0.f, 0.f), x1 = x0;
            if (row0 + row < N) {
                x0 = ((const float4*)X)[(size_t)(row0 + row) * 32 + ch * 2];
                x1 = ((const float4*)X)[(size_t)(row0 + row) * 32 + ch * 2 + 1];
            }
            uint4 hi, lo;
            split8(x0, x1, hi, lo);
            uint32_t sw = xoff(row, ch);
            *(uint4*)(smem + XHI_OFF + sw) = hi;
            *(uint4*)(smem + XLO_OFF + sw) = lo;
        }
        __syncthreads();

        float acc[2][4][4];
        #pragma unroll
        for (int mt = 0; mt < 2; mt++)
            #pragma unroll
            for (int nt = 0; nt < 4; nt++)
                #pragma unroll
                for (int q = 0; q < 4; q++) acc[mt][nt][q] = 0.f;

        #pragma unroll
        for (int ks = 0; ks < 8; ks++) {
            uint32_t ah[2][4], al[2][4];
            int arow = wm * 32 + (lane & 15);
            int ach = ks * 2 + (lane >> 4);
            #pragma unroll
            for (int mt = 0; mt < 2; mt++) {
                uint32_t sw = xoff(arow + mt * 16, ach);
                LDMATRIX4(ah[mt], sbase + XHI_OFF + sw);
                LDMATRIX4(al[mt], sbase + XLO_OFF + sw);
            }
            uint32_t bh[4][2], bl[4][2];
            #pragma unroll
            for (int nt = 0; nt < 4; nt++) {
                uint32_t off_h = BF_OFF + (((0 * 8 + ks) * 16 + wn * 4 + nt) * 32 + lane) * 8;
                uint32_t off_l = BF_OFF + (((1 * 8 + ks) * 16 + wn * 4 + nt) * 32 + lane) * 8;
                asm volatile("ld.shared.v2.u32 {%0,%1}, [%2];"
                             : "=r"(bh[nt][0]), "=r"(bh[nt][1]) : "r"(sbase + off_h));
                asm volatile("ld.shared.v2.u32 {%0,%1}, [%2];"
                             : "=r"(bl[nt][0]), "=r"(bl[nt][1]) : "r"(sbase + off_l));
            }
            #pragma unroll
            for (int mt = 0; mt < 2; mt++)
                #pragma unroll
                for (int nt = 0; nt < 4; nt++) {
                    MMA_BF16(acc[mt][nt], ah[mt], bh[nt]);
                    MMA_BF16(acc[mt][nt], ah[mt], bl[nt]);
                    MMA_BF16(acc[mt][nt], al[mt], bh[nt]);
                }
        }

        // stage D into ht (overlaps Xhi/Xlo; MMA reads are done)
        __syncthreads();
        #pragma unroll
        for (int mt = 0; mt < 2; mt++)
            #pragma unroll
            for (int nt = 0; nt < 4; nt++) {
                int r0 = wm * 32 + mt * 16 + (lane >> 2);
                int cc = wn * 32 + nt * 8 + (lane & 3) * 2;
                *(float2*)&ht[r0 * HT_STRIDE + cc]       = make_float2(acc[mt][nt][0], acc[mt][nt][1]);
                *(float2*)&ht[(r0 + 8) * HT_STRIDE + cc] = make_float2(acc[mt][nt][2], acc[mt][nt][3]);
            }
        __syncthreads();

        // epilogue: thread = (row, col-quarter): row=tid>>2, q=tid&3 owns 32 cols
        int row = tid >> 2;
        int q = tid & 3;
        int cq = q * 32;
        int grow = row0 + row;
        bool ok = grow < N;

        float hv[32];
        #pragma unroll
        for (int j = 0; j < 8; j++) {
            float4 a = *(float4*)&ht[row * HT_STRIDE + cq + j * 4];
            hv[j * 4 + 0] = a.x + sb[cq + j * 4 + 0];
            hv[j * 4 + 1] = a.y + sb[cq + j * 4 + 1];
            hv[j * 4 + 2] = a.z + sb[cq + j * 4 + 2];
            hv[j * 4 + 3] = a.w + sb[cq + j * 4 + 3];
        }

        if (ok) {
            #pragma unroll
            for (int j = 0; j < 8; j++) {
                float4 v = make_float4(hv[j*4], hv[j*4+1], hv[j*4+2], hv[j*4+3]);
                ((float4*)out)[(size_t)grow * 32 + q * 8 + j] = v;
                if (q == 0)
                    ((float4*)g_h32)[grow * 8 + j] = v;
            }
        }

        float ps[NHEAD], pd[NHEAD];
        #pragma unroll
        for (int hh = 0; hh < NHEAD; hh++) {
            const float* was = &sWa[hh * 2 * DIM + cq];
            const float* wad = &sWa[hh * 2 * DIM + DIM + cq];
            float s1 = 0.f, s2 = 0.f;
            #pragma unroll
            for (int j = 0; j < 32; j += 4) {
                float4 w4 = *(const float4*)&was[j];
                float4 d4 = *(const float4*)&wad[j];
                s1 += hv[j] * w4.x + hv[j+1] * w4.y + hv[j+2] * w4.z + hv[j+3] * w4.w;
                s2 += hv[j] * d4.x + hv[j+1] * d4.y + hv[j+2] * d4.z + hv[j+3] * d4.w;
            }
            // reduce across the 4 col-quarter threads (same warp, width 4)
            #pragma unroll
            for (int off = 2; off; off >>= 1) {
                s1 += __shfl_down_sync(0xffffffffu, s1, off, 4);
                s2 += __shfl_down_sync(0xffffffffu, s2, off, 4);
            }
            ps[hh] = s1; pd[hh] = s2;
        }
        if (q == 0 && ok) {
            ((float4*)g_eas)[grow] = make_float4(__expf(ps[0]), __expf(ps[1]), __expf(ps[2]), __expf(ps[3]));
            ((float4*)g_ead)[grow] = make_float4(__expf(pd[0]), __expf(pd[1]), __expf(pd[2]), __expf(pd[3]));
        }
    }
}

// ---------------- K2: decode (forked) ----------------
__global__ __launch_bounds__(256)
void decode_kernel(const void* __restrict__ ei, int E) {
    int e = blockIdx.x * 256 + threadIdx.x;
    if (e >= E) return;
    int s, d;
    if (g_is64) {
        const long long* p = (const long long*)ei;
        s = (int)p[e]; d = (int)p[E + e];
    } else {
        const int* p = (const int*)ei;
        s = p[e]; d = p[E + e];
    }
    g_sd[e] = make_int2(s, d);
    g_rk[e] = atomicAdd(&g_cnt[d], 1);
}

// ---------------- K3a/K3b: scans ----------------
__global__ __launch_bounds__(256)
void scanA_kernel() {
    int t = threadIdx.x;
    int i = blockIdx.x * 256 + t;
    int v = (i < NMAX) ? g_cnt[i] : 0;
    int x = v;
    #pragma unroll
    for (int off = 1; off < 32; off <<= 1) {
        int y = __shfl_up_sync(0xffffffffu, x, off);
        if ((t & 31) >= off) x += y;
    }
    __shared__ int wsum[8];
    if ((t & 31) == 31) wsum[t >> 5] = x;
    __syncthreads();
    if (t < 8) {
        int y = wsum[t], z = y;
        #pragma unroll
        for (int off = 1; off < 8; off <<= 1) {
            int q = __shfl_up_sync(0xffu, z, off);
            if (t >= off) z += q;
        }
        wsum[t] = z - y;
    }
    __syncthreads();
    int excl = x - v + wsum[t >> 5];
    if (i < NMAX) g_intra[i] = excl;
    if (t == 255) g_bsum[blockIdx.x] = excl + v;
}

__global__ __launch_bounds__(512)
void scanB_kernel() {
    __shared__ int s0[512], s1[512];
    int t = threadIdx.x;
    int v = (t < NBLK) ? g_bsum[t] : 0;
    s0[t] = v;
    __syncthreads();
    int* a = s0; int* b = s1;
    for (int off = 1; off < 512; off <<= 1) {
        int x = a[t];
        if (t >= off) x += a[t - off];
        b[t] = x;
        __syncthreads();
        int* tmp = a; a = b; b = tmp;
    }
    if (t < NBLK) g_boff[t] = a[t] - v;
}

// ---------------- K4: CSR fill (forked; atomic-free) ----------------
__global__ __launch_bounds__(256)
void fill_kernel(int E) {
    int e = blockIdx.x * 256 + threadIdx.x;
    if (e >= E) return;
    int2 sd = g_sd[e];
    g_esrc[g_boff[sd.y >> 8] + g_intra[sd.y] + g_rk[e]] = sd.x;
}

// ---------------- K5: softmax sums ----------------
__global__ __launch_bounds__(256)
void sums_kernel(int E) {
    int e = blockIdx.x * 256 + threadIdx.x;
    float v0 = 0.f, v1 = 0.f, v2 = 0.f, v3 = 0.f;
    if (e < E) {
        int2 sd = g_sd[e];
        float4 as = ((const float4*)g_eas)[sd.x];
        float4 ad = ((const float4*)g_ead)[sd.y];
        v0 = as.x * ad.x; v1 = as.y * ad.y; v2 = as.z * ad.z; v3 = as.w * ad.w;
    }
    #pragma unroll
    for (int off = 16; off; off >>= 1) {
        v0 += __shfl_xor_sync(0xffffffffu, v0, off);
        v1 += __shfl_xor_sync(0xffffffffu, v1, off);
        v2 += __shfl_xor_sync(0xffffffffu, v2, off);
        v3 += __shfl_xor_sync(0xffffffffu, v3, off);
    }
    __shared__ float ss[NHEAD];
    if (threadIdx.x < NHEAD) ss[threadIdx.x] = 0.f;
    __syncthreads();
    if ((threadIdx.x & 31) == 0) {
        atomicAdd(&ss[0], v0); atomicAdd(&ss[1], v1);
        atomicAdd(&ss[2], v2); atomicAdd(&ss[3], v3);
    }
    __syncthreads();
    if (threadIdx.x < NHEAD) atomicAdd(&g_sums[threadIdx.x], ss[threadIdx.x]);
}

// ---------------- K6: gather (proven simple loop) ----------------
__global__ __launch_bounds__(256)
void gather_kernel(float* __restrict__ out, int N) {
    int d = (blockIdx.x * 256 + threadIdx.x) >> 5;
    int lane = threadIdx.x & 31;
    if (d >= N) return;
    int n = g_cnt[d];
    if (n == 0) return;
    int base = g_boff[d >> 8] + g_intra[d];
    float4 fe = ((const float4*)g_ead)[d];
    float4 sm4 = *(const float4*)g_sums;
    float w0 = __fdividef(fe.x, sm4.x);
    float w1 = __fdividef(fe.y, sm4.y);
    float w2 = __fdividef(fe.z, sm4.z);
    float w3 = __fdividef(fe.w, sm4.w);
    float a0 = 0.f, a1 = 0.f, a2 = 0.f, a3 = 0.f;
    for (int i = 0; i < n; i++) {
        int s = g_esrc[base + i];
        float v = g_h32[s * HD + lane];
        float4 ea = ((const float4*)g_eas)[s];
        a0 += v * ea.x; a1 += v * ea.y; a2 += v * ea.z; a3 += v * ea.w;
    }
    float* o = out + (size_t)d * DIM + lane;
    o[0]  += a0 * w0;
    o[32] += a1 * w1;
    o[64] += a2 * w2;
    o[96] += a3 * w3;
}

// ---------------- launch ----------------
// submission order: prep(1) decode(2) scanA(3) gemm(4!) scanB(5) fill(6) sums(7) gather(8)
extern "C" void kernel_launch(void* const* d_in, const int* in_sizes, int n_in,
                              void* d_out, int out_size) {
    const float* X    = (const float*)d_in[0];
    const void*  ei   = d_in[1];
    const float* Wlin = (const float*)d_in[2];
    const float* blin = (const float*)d_in[3];
    const float* Watt = (const float*)d_in[4];
    float* out = (float*)d_out;

    int N = in_sizes[0] / DIM;
    int E = in_sizes[1] / 2;
    int NT = (N + 127) / 128;
    int grid = NT < PERSIST_TC ? NT : PERSIST_TC;

    static cudaStream_t s1 = nullptr;
    static cudaEvent_t evFork = nullptr, evP = nullptr, evDec = nullptr, evJoin = nullptr;
    if (s1 == nullptr) {
        cudaStreamCreateWithFlags(&s1, cudaStreamNonBlocking);
        cudaEventCreateWithFlags(&evFork, cudaEventDisableTiming);
        cudaEventCreateWithFlags(&evP, cudaEventDisableTiming);
        cudaEventCreateWithFlags(&evDec, cudaEventDisableTiming);
        cudaEventCreateWithFlags(&evJoin, cudaEventDisableTiming);
    }

    cudaFuncSetAttribute(gemm_kernel,
                         cudaFuncAttributeMaxDynamicSharedMemorySize, GS_TOTAL);

    // capture-legal fork from origin stream
    cudaEventRecord(evFork, 0);
    cudaStreamWaitEvent(s1, evFork, 0);

    // s1: prep (Bfrag + counters), then edge chain
    prep_kernel<<<200, 512, 0, s1>>>(Wlin, (const unsigned int*)ei);   // #1
    cudaEventRecord(evP, s1);
    decode_kernel<<<(E + 255) / 256, 256, 0, s1>>>(ei, E);             // #2
    cudaEventRecord(evDec, s1);
    scanA_kernel<<<NBLK, 256, 0, s1>>>();                              // #3

    // s0: persistent tensor-core GEMM (waits on prep) -> ncu launch #4
    cudaStreamWaitEvent(0, evP, 0);
    gemm_kernel<<<grid, TCTHREADS, GS_TOTAL>>>(X, blin, Watt, out, N, NT); // #4

    scanB_kernel<<<1, 512, 0, s1>>>();                                 // #5
    fill_kernel<<<(E + 255) / 256, 256, 0, s1>>>(E);                   // #6
    cudaEventRecord(evJoin, s1);

    // s0: sums (after gemm in-stream, + decode), then gather (after fill)
    cudaStreamWaitEvent(0, evDec, 0);
    sums_kernel<<<(E + 255) / 256, 256>>>(E);                          // #7
    cudaStreamWaitEvent(0, evJoin, 0);
    gather_kernel<<<(N * 32 + 255) / 256, 256>>>(out, N);              // #8
}

// round 17
// speedup vs baseline: 1.3558x; 1.3558x over previous
#include <cuda_runtime.h>
#include <cuda_fp16.h>
#include <cstdint>

#define NMAX   100000
#define EMAX   500000
#define DIM    128
#define NHEAD  4
#define HD     32
#define NBLK   391          // ceil(NMAX/256)

// ---------------- scratch ----------------
__device__ float g_h32[NMAX * HD];
__device__ float g_eas[NMAX * NHEAD];
__device__ float g_ead[NMAX * NHEAD];
__device__ float g_sums[NHEAD];
__device__ int   g_is64;
__device__ int   g_cnt[NMAX];
__device__ int   g_intra[NMAX];
__device__ int   g_bsum[512];
__device__ int   g_boff[512];
__device__ int2  g_sd[EMAX];
__device__ int   g_rk[EMAX];
__device__ int   g_esrc[EMAX];
// W fragments (fp16, single rounding): [ks][nt][lane][reg] u32 (32KB)
__device__ __align__(16) uint32_t g_Bfrag[8 * 16 * 32 * 2];

// ---------------- K0: prep (s1: Bfrag build + counters + sniff) ----------------
__global__ void prep_kernel(const float* __restrict__ Wlin,
                            const unsigned int* __restrict__ ei_raw) {
    int tid = blockIdx.x * blockDim.x + threadIdx.x;
    int total = gridDim.x * blockDim.x;
    for (int i = tid; i < NMAX; i += total) g_cnt[i] = 0;
    // W[n][k] is exactly col-major B for m16n8k16.row.col
    for (int i = tid; i < 8192; i += total) {
        int reg   = i & 1;
        int lane  = (i >> 1) & 31;
        int nt    = (i >> 6) & 15;
        int ks    = (i >> 10) & 7;
        int n  = nt * 8 + (lane >> 2);
        int k0 = ks * 16 + (lane & 3) * 2 + reg * 8;
        __half h0 = __float2half_rn(Wlin[n * DIM + k0]);
        __half h1 = __float2half_rn(Wlin[n * DIM + k0 + 1]);
        unsigned short b0 = *(unsigned short*)&h0;
        unsigned short b1 = *(unsigned short*)&h1;
        g_Bfrag[i] = (uint32_t)b0 | ((uint32_t)b1 << 16);
    }
    if (blockIdx.x == 0) {
        if (threadIdx.x < NHEAD) g_sums[threadIdx.x] = 0.0f;
        if (threadIdx.x == 0) {
            int all0 = 1;
            for (int i = 0; i < 64; i++)
                if (ei_raw[2 * i + 1] != 0u) { all0 = 0; break; }
            g_is64 = all0;
        }
    }
}

// ---------------- K1: persistent mma.sync fp16 2-product GEMM ----------------
// smem: Bfrag [0,32K) staged ONCE; Xhi [32K,64K); Xlo [64K,96K)
// epilogue ht f32[128][132] reuses [32K, 32K+67584)
#define BF_OFF  0
#define XHI_OFF 32768
#define XLO_OFF 65536
#define HT_STRIDE 132
#define GS_TOTAL (32768 + 128 * HT_STRIDE * 4)
#define PERSIST_TC 148

__device__ __forceinline__ uint32_t smem_u32(const void* p) {
    uint32_t a;
    asm("{ .reg .u64 t; cvta.to.shared.u64 t, %1; cvt.u32.u64 %0, t; }" : "=r"(a) : "l"(p));
    return a;
}

// 16B-granule XOR swizzle in a 128x128-f16 tile (row stride 256B)
__device__ __forceinline__ uint32_t xoff(int row, int ch) {
    return (uint32_t)(row * 256 + ((ch ^ (row & 7)) << 4));
}

__device__ __forceinline__ void split8(const float4& a, const float4& b,
                                       uint4& hi, uint4& lo) {
    float v[8] = {a.x, a.y, a.z, a.w, b.x, b.y, b.z, b.w};
    unsigned short h[8], l[8];
    #pragma unroll
    for (int i = 0; i < 8; i++) {
        __half bh = __float2half_rn(v[i]);
        float r = v[i] - __half2float(bh);
        __half bl = __float2half_rn(r);
        h[i] = *(unsigned short*)&bh;
        l[i] = *(unsigned short*)&bl;
    }
    hi = make_uint4((uint32_t)h[0] | ((uint32_t)h[1] << 16),
                    (uint32_t)h[2] | ((uint32_t)h[3] << 16),
                    (uint32_t)h[4] | ((uint32_t)h[5] << 16),
                    (uint32_t)h[6] | ((uint32_t)h[7] << 16));
    lo = make_uint4((uint32_t)l[0] | ((uint32_t)l[1] << 16),
                    (uint32_t)l[2] | ((uint32_t)l[3] << 16),
                    (uint32_t)l[4] | ((uint32_t)l[5] << 16),
                    (uint32_t)l[6] | ((uint32_t)l[7] << 16));
}

#define LDMATRIX4(f, addr) \
    asm volatile("ldmatrix.sync.aligned.m8n8.x4.shared.b16 {%0,%1,%2,%3}, [%4];" \
        : "=r"((f)[0]), "=r"((f)[1]), "=r"((f)[2]), "=r"((f)[3]) : "r"(addr))

#define MMA_F16(d, a, b) \
    asm volatile("mma.sync.aligned.m16n8k16.row.col.f32.f16.f16.f32 " \
        "{%0,%1,%2,%3}, {%4,%5,%6,%7}, {%8,%9}, {%0,%1,%2,%3};" \
        : "+f"((d)[0]), "+f"((d)[1]), "+f"((d)[2]), "+f"((d)[3]) \
        : "r"((a)[0]), "r"((a)[1]), "r"((a)[2]), "r"((a)[3]), \
          "r"((b)[0]), "r"((b)[1]))

__global__ __launch_bounds__(256)
void gemm_kernel(const float* __restrict__ X,
                 const float* __restrict__ blin,
                 const float* __restrict__ Watt,
                 float* __restrict__ out, int N, int NT) {
    extern __shared__ char smem[];
    float* ht = (float*)(smem + XHI_OFF);
    __shared__ float sWa[NHEAD * 2 * DIM];
    __shared__ float sb[DIM];
    uint32_t sbase = smem_u32(smem);
    int tid = threadIdx.x;
    int wid = tid >> 5, lane = tid & 31;
    int wm = wid >> 2, wn = wid & 3;      // warp tile m64 x n32
    int tx = tid & 15, ty = tid >> 4;
    int c = tx * 8;

    for (int i = tid; i < NHEAD * 2 * DIM; i += 256) sWa[i] = Watt[i];
    if (tid < DIM) sb[tid] = blin[tid];

    // stage W fragments ONCE per persistent CTA (32KB)
    {
        const uint4* src = (const uint4*)g_Bfrag;
        uint4* dst = (uint4*)(smem + BF_OFF);
        for (int i = tid; i < 2048; i += 256) dst[i] = src[i];
    }

    for (int tile = blockIdx.x; tile < NT; tile += gridDim.x) {
        int row0 = tile * 128;

        __syncthreads();   // previous tile's ht reads done; Bfrag staged (first iter)

        // load + split X tile into Xhi/Xlo swizzled smem (fp16 exact split)
        for (int i = tid; i < 2048; i += 256) {
            int row = i >> 4, ch = i & 15;
            float4 x0 = make_float4(0.f, 0.f, 0.f, 0.f), x1 = x0;
            if (row0 + row < N) {
                x0 = ((const float4*)X)[(size_t)(row0 + row) * 32 + ch * 2];
                x1 = ((const float4*)X)[(size_t)(row0 + row) * 32 + ch * 2 + 1];
            }
            uint4 hi, lo;
            split8(x0, x1, hi, lo);
            uint32_t sw = xoff(row, ch);
            *(uint4*)(smem + XHI_OFF + sw) = hi;
            *(uint4*)(smem + XLO_OFF + sw) = lo;
        }
        __syncthreads();

        float acc[4][4][4];
        #pragma unroll
        for (int mt = 0; mt < 4; mt++)
            #pragma unroll
            for (int nt = 0; nt < 4; nt++)
                #pragma unroll
                for (int q = 0; q < 4; q++) acc[mt][nt][q] = 0.f;

        #pragma unroll
        for (int ks = 0; ks < 8; ks++) {
            uint32_t ah[4][4], al[4][4];
            int arow = wm * 64 + (lane & 15);
            int ach = ks * 2 + (lane >> 4);
            #pragma unroll
            for (int mt = 0; mt < 4; mt++) {
                uint32_t sw = xoff(arow + mt * 16, ach);
                LDMATRIX4(ah[mt], sbase + XHI_OFF + sw);
                LDMATRIX4(al[mt], sbase + XLO_OFF + sw);
            }
            uint32_t bh[4][2];
            #pragma unroll
            for (int nt = 0; nt < 4; nt++) {
                uint32_t off_h = BF_OFF + ((ks * 16 + wn * 4 + nt) * 32 + lane) * 8;
                asm volatile("ld.shared.v2.u32 {%0,%1}, [%2];"
                             : "=r"(bh[nt][0]), "=r"(bh[nt][1]) : "r"(sbase + off_h));
            }
            #pragma unroll
            for (int mt = 0; mt < 4; mt++)
                #pragma unroll
                for (int nt = 0; nt < 4; nt++) {
                    MMA_F16(acc[mt][nt], ah[mt], bh[nt]);
                    MMA_F16(acc[mt][nt], al[mt], bh[nt]);
                }
        }

        // stage D into ht (overlaps Xhi region; MMA reads are done)
        __syncthreads();
        #pragma unroll
        for (int mt = 0; mt < 4; mt++)
            #pragma unroll
            for (int nt = 0; nt < 4; nt++) {
                int r0 = wm * 64 + mt * 16 + (lane >> 2);
                int cc = wn * 32 + nt * 8 + (lane & 3) * 2;
                *(float2*)&ht[r0 * HT_STRIDE + cc]       = make_float2(acc[mt][nt][0], acc[mt][nt][1]);
                *(float2*)&ht[(r0 + 8) * HT_STRIDE + cc] = make_float2(acc[mt][nt][2], acc[mt][nt][3]);
            }
        __syncthreads();

        // epilogue: tx owns 8 cols, ty owns 8 rows
        float hv[8][8];
        #pragma unroll
        for (int r = 0; r < 8; r++) {
            float4 a = *(float4*)&ht[(ty * 8 + r) * HT_STRIDE + c];
            float4 b = *(float4*)&ht[(ty * 8 + r) * HT_STRIDE + c + 4];
            hv[r][0] = a.x + sb[c];     hv[r][1] = a.y + sb[c + 1];
            hv[r][2] = a.z + sb[c + 2]; hv[r][3] = a.w + sb[c + 3];
            hv[r][4] = b.x + sb[c + 4]; hv[r][5] = b.y + sb[c + 5];
            hv[r][6] = b.z + sb[c + 6]; hv[r][7] = b.w + sb[c + 7];
        }

        #pragma unroll
        for (int r = 0; r < 8; r++) {
            int row = row0 + ty * 8 + r;
            if (row < N) {
                float4 v0 = make_float4(hv[r][0], hv[r][1], hv[r][2], hv[r][3]);
                float4 v1 = make_float4(hv[r][4], hv[r][5], hv[r][6], hv[r][7]);
                ((float4*)out)[(size_t)row * 32 + tx * 2]     = v0;
                ((float4*)out)[(size_t)row * 32 + tx * 2 + 1] = v1;
                if (tx < 4) {
                    ((float4*)g_h32)[row * 8 + tx * 2]     = v0;
                    ((float4*)g_h32)[row * 8 + tx * 2 + 1] = v1;
                }
            }
        }

        #pragma unroll
        for (int r = 0; r < 8; r++) {
            int row = row0 + ty * 8 + r;
            float ps[NHEAD], pd[NHEAD];
            #pragma unroll
            for (int hh = 0; hh < NHEAD; hh++) {
                float s1 = 0.f, s2 = 0.f;
                #pragma unroll
                for (int j = 0; j < 8; j++) {
                    s1 += hv[r][j] * sWa[hh * 2 * DIM + c + j];
                    s2 += hv[r][j] * sWa[hh * 2 * DIM + DIM + c + j];
                }
                #pragma unroll
                for (int off = 8; off; off >>= 1) {
                    s1 += __shfl_down_sync(0xffffffffu, s1, off, 16);
                    s2 += __shfl_down_sync(0xffffffffu, s2, off, 16);
                }
                ps[hh] = s1; pd[hh] = s2;
            }
            if (tx == 0 && row < N) {
                ((float4*)g_eas)[row] = make_float4(__expf(ps[0]), __expf(ps[1]), __expf(ps[2]), __expf(ps[3]));
                ((float4*)g_ead)[row] = make_float4(__expf(pd[0]), __expf(pd[1]), __expf(pd[2]), __expf(pd[3]));
            }
        }
    }
}

// ---------------- K2: decode (forked) ----------------
__global__ __launch_bounds__(256)
void decode_kernel(const void* __restrict__ ei, int E) {
    int e = blockIdx.x * 256 + threadIdx.x;
    if (e >= E) return;
    int s, d;
    if (g_is64) {
        const long long* p = (const long long*)ei;
        s = (int)p[e]; d = (int)p[E + e];
    } else {
        const int* p = (const int*)ei;
        s = p[e]; d = p[E + e];
    }
    g_sd[e] = make_int2(s, d);
    g_rk[e] = atomicAdd(&g_cnt[d], 1);
}

// ---------------- K3a/K3b: scans ----------------
__global__ __launch_bounds__(256)
void scanA_kernel() {
    int t = threadIdx.x;
    int i = blockIdx.x * 256 + t;
    int v = (i < NMAX) ? g_cnt[i] : 0;
    int x = v;
    #pragma unroll
    for (int off = 1; off < 32; off <<= 1) {
        int y = __shfl_up_sync(0xffffffffu, x, off);
        if ((t & 31) >= off) x += y;
    }
    __shared__ int wsum[8];
    if ((t & 31) == 31) wsum[t >> 5] = x;
    __syncthreads();
    if (t < 8) {
        int y = wsum[t], z = y;
        #pragma unroll
        for (int off = 1; off < 8; off <<= 1) {
            int q = __shfl_up_sync(0xffu, z, off);
            if (t >= off) z += q;
        }
        wsum[t] = z - y;
    }
    __syncthreads();
    int excl = x - v + wsum[t >> 5];
    if (i < NMAX) g_intra[i] = excl;
    if (t == 255) g_bsum[blockIdx.x] = excl + v;
}

__global__ __launch_bounds__(512)
void scanB_kernel() {
    __shared__ int s0[512], s1[512];
    int t = threadIdx.x;
    int v = (t < NBLK) ? g_bsum[t] : 0;
    s0[t] = v;
    __syncthreads();
    int* a = s0; int* b = s1;
    for (int off = 1; off < 512; off <<= 1) {
        int x = a[t];
        if (t >= off) x += a[t - off];
        b[t] = x;
        __syncthreads();
        int* tmp = a; a = b; b = tmp;
    }
    if (t < NBLK) g_boff[t] = a[t] - v;
}

// ---------------- K4: CSR fill (forked; atomic-free) ----------------
__global__ __launch_bounds__(256)
void fill_kernel(int E) {
    int e = blockIdx.x * 256 + threadIdx.x;
    if (e >= E) return;
    int2 sd = g_sd[e];
    g_esrc[g_boff[sd.y >> 8] + g_intra[sd.y] + g_rk[e]] = sd.x;
}

// ---------------- K5: softmax sums ----------------
__global__ __launch_bounds__(256)
void sums_kernel(int E) {
    int e = blockIdx.x * 256 + threadIdx.x;
    float v0 = 0.f, v1 = 0.f, v2 = 0.f, v3 = 0.f;
    if (e < E) {
        int2 sd = g_sd[e];
        float4 as = ((const float4*)g_eas)[sd.x];
        float4 ad = ((const float4*)g_ead)[sd.y];
        v0 = as.x * ad.x; v1 = as.y * ad.y; v2 = as.z * ad.z; v3 = as.w * ad.w;
    }
    #pragma unroll
    for (int off = 16; off; off >>= 1) {
        v0 += __shfl_xor_sync(0xffffffffu, v0, off);
        v1 += __shfl_xor_sync(0xffffffffu, v1, off);
        v2 += __shfl_xor_sync(0xffffffffu, v2, off);
        v3 += __shfl_xor_sync(0xffffffffu, v3, off);
    }
    __shared__ float ss[NHEAD];
    if (threadIdx.x < NHEAD) ss[threadIdx.x] = 0.f;
    __syncthreads();
    if ((threadIdx.x & 31) == 0) {
        atomicAdd(&ss[0], v0); atomicAdd(&ss[1], v1);
        atomicAdd(&ss[2], v2); atomicAdd(&ss[3], v3);
    }
    __syncthreads();
    if (threadIdx.x < NHEAD) atomicAdd(&g_sums[threadIdx.x], ss[threadIdx.x]);
}

// ---------------- K6: gather (proven simple loop) ----------------
__global__ __launch_bounds__(256)
void gather_kernel(float* __restrict__ out, int N) {
    int d = (blockIdx.x * 256 + threadIdx.x) >> 5;
    int lane = threadIdx.x & 31;
    if (d >= N) return;
    int n = g_cnt[d];
    if (n == 0) return;
    int base = g_boff[d >> 8] + g_intra[d];
    float4 fe = ((const float4*)g_ead)[d];
    float4 sm4 = *(const float4*)g_sums;
    float w0 = __fdividef(fe.x, sm4.x);
    float w1 = __fdividef(fe.y, sm4.y);
    float w2 = __fdividef(fe.z, sm4.z);
    float w3 = __fdividef(fe.w, sm4.w);
    float a0 = 0.f, a1 = 0.f, a2 = 0.f, a3 = 0.f;
    for (int i = 0; i < n; i++) {
        int s = g_esrc[base + i];
        float v = g_h32[s * HD + lane];
        float4 ea = ((const float4*)g_eas)[s];
        a0 += v * ea.x; a1 += v * ea.y; a2 += v * ea.z; a3 += v * ea.w;
    }
    float* o = out + (size_t)d * DIM + lane;
    o[0]  += a0 * w0;
    o[32] += a1 * w1;
    o[64] += a2 * w2;
    o[96] += a3 * w3;
}

// ---------------- launch ----------------
// submission order: prep(1) decode(2) scanA(3) gemm(4!) scanB(5) fill(6) sums(7) gather(8)
extern "C" void kernel_launch(void* const* d_in, const int* in_sizes, int n_in,
                              void* d_out, int out_size) {
    const float* X    = (const float*)d_in[0];
    const void*  ei   = d_in[1];
    const float* Wlin = (const float*)d_in[2];
    const float* blin = (const float*)d_in[3];
    const float* Watt = (const float*)d_in[4];
    float* out = (float*)d_out;

    int N = in_sizes[0] / DIM;
    int E = in_sizes[1] / 2;
    int NT = (N + 127) / 128;
    int grid = NT < PERSIST_TC ? NT : PERSIST_TC;

    static cudaStream_t s1 = nullptr;
    static cudaEvent_t evFork = nullptr, evP = nullptr, evDec = nullptr, evJoin = nullptr;
    if (s1 == nullptr) {
        cudaStreamCreateWithFlags(&s1, cudaStreamNonBlocking);
        cudaEventCreateWithFlags(&evFork, cudaEventDisableTiming);
        cudaEventCreateWithFlags(&evP, cudaEventDisableTiming);
        cudaEventCreateWithFlags(&evDec, cudaEventDisableTiming);
        cudaEventCreateWithFlags(&evJoin, cudaEventDisableTiming);
    }

    cudaFuncSetAttribute(gemm_kernel,
                         cudaFuncAttributeMaxDynamicSharedMemorySize, GS_TOTAL);

    // capture-legal fork from origin stream
    cudaEventRecord(evFork, 0);
    cudaStreamWaitEvent(s1, evFork, 0);

    // s1: prep (Bfrag + counters), then edge chain
    prep_kernel<<<200, 512, 0, s1>>>(Wlin, (const unsigned int*)ei);   // #1
    cudaEventRecord(evP, s1);
    decode_kernel<<<(E + 255) / 256, 256, 0, s1>>>(ei, E);             // #2
    cudaEventRecord(evDec, s1);
    scanA_kernel<<<NBLK, 256, 0, s1>>>();                              // #3

    // s0: persistent tensor-core GEMM (waits on prep) -> ncu launch #4
    cudaStreamWaitEvent(0, evP, 0);
    gemm_kernel<<<grid, 256, GS_TOTAL>>>(X, blin, Watt, out, N, NT);   // #4

    scanB_kernel<<<1, 512, 0, s1>>>();                                 // #5
    fill_kernel<<<(E + 255) / 256, 256, 0, s1>>>(E);                   // #6
    cudaEventRecord(evJoin, s1);

    // s0: sums (after gemm in-stream, + decode), then gather (after fill)
    cudaStreamWaitEvent(0, evDec, 0);
    sums_kernel<<<(E + 255) / 256, 256>>>(E);                          // #7
    cudaStreamWaitEvent(0, evJoin, 0);
    gather_kernel<<<(N * 32 + 255) / 256, 256>>>(out, N);              // #8
}